// round 1
// baseline (speedup 1.0000x reference)
#include <cuda_runtime.h>

// ---------------------------------------------------------------------------
// SimpleCnn: conv(3->64,3x3,p1)+leaky+pool2 -> conv(64->64,3x3,p1)+leaky+pool2
//            -> flatten -> FC(200704->10)
// Shapes: x[32,3,224,224] w1[64,3,3,3] b1[64] w2[64,64,3,3] b2[64]
//         wfc[200704,10] bfc[10]  out[32,10] fp32
// ---------------------------------------------------------------------------

#define NB   32
#define C1   3
#define OCH  64
#define HA   224   // conv1 input spatial
#define HB   112   // conv1 pooled / conv2 input spatial
#define HC   56    // conv2 pooled spatial
#define FLATK (OCH*HC*HC)   // 200704
#define NCHUNK 98           // 200704 / 2048
#define CHUNK  2048

// Intermediate scratch (device globals: no allocation allowed in kernel_launch)
__device__ float g_h1[NB*OCH*HB*HB];          // 102.8 MB
__device__ float g_h2[NB*OCH*HC*HC];          //  25.7 MB
__device__ float g_fcp[NB*NCHUNK*10];         //  tiny

// ---------------------------------------------------------------------------
// Fused conv3x3(pad1) + bias + leakyReLU(0.01) + maxpool2x2
// Block: 14x14 pooled tile (196 threads), OCG=8 output channels per block.
// Input tile staged in shared: ICC channels x 30x30 (rows padded to 32).
// ---------------------------------------------------------------------------
#define TS  14
#define OCG 8

template<int CIN, int ICC, int HIN>
__global__ void __launch_bounds__(TS*TS)
conv_lrelu_pool(const float* __restrict__ x,
                const float* __restrict__ w,
                const float* __restrict__ bias,
                float* __restrict__ out)
{
    constexpr int HP    = HIN / 2;       // pooled spatial
    constexpr int TILES = HP / TS;       // exact: 112/14=8, 56/14=4

    __shared__ float s_in[ICC][30][32];
    __shared__ float s_w[OCG*ICC*9];

    const int bidx = blockIdx.x;
    const int tile = bidx % (TILES*TILES);
    const int ocg  = (bidx / (TILES*TILES)) % (OCH/OCG);
    const int b    =  bidx / (TILES*TILES*(OCH/OCG));
    const int ty0  = (tile / TILES) * TS;
    const int tx0  = (tile % TILES) * TS;

    const int tid = threadIdx.x;         // 0..195
    const int tx  = tid % TS;
    const int ty  = tid / TS;

    float acc[OCG][4];
    #pragma unroll
    for (int o = 0; o < OCG; o++)
        #pragma unroll
        for (int k = 0; k < 4; k++) acc[o][k] = 0.f;

    const float* xb = x + (long)b * CIN * HIN * HIN;

    for (int c0 = 0; c0 < CIN; c0 += ICC) {
        __syncthreads();
        // stage input tile (zero-fill padding)
        for (int i = tid; i < ICC*30*30; i += TS*TS) {
            const int c  = i / 900;
            const int r  = (i % 900) / 30;
            const int cc = i % 30;
            const int gy = 2*ty0 - 1 + r;
            const int gx = 2*tx0 - 1 + cc;
            float v = 0.f;
            if (gy >= 0 && gy < HIN && gx >= 0 && gx < HIN)
                v = xb[(c0 + c) * HIN * HIN + gy * HIN + gx];
            s_in[c][r][cc] = v;
        }
        // stage weights for this (ocg, ic-chunk)
        for (int i = tid; i < OCG*ICC*9; i += TS*TS) {
            const int o = i / (ICC*9);
            const int r = i % (ICC*9);
            const int c = r / 9;
            const int k = r % 9;
            s_w[i] = w[((ocg*OCG + o) * CIN + c0 + c) * 9 + k];
        }
        __syncthreads();

        #pragma unroll
        for (int c = 0; c < ICC; c++) {
            float v[4][4];
            #pragma unroll
            for (int i = 0; i < 4; i++)
                #pragma unroll
                for (int j = 0; j < 4; j++)
                    v[i][j] = s_in[c][2*ty + i][2*tx + j];

            #pragma unroll
            for (int o = 0; o < OCG; o++) {
                float wr[9];
                #pragma unroll
                for (int k = 0; k < 9; k++) wr[k] = s_w[(o*ICC + c)*9 + k];
                #pragma unroll
                for (int ky = 0; ky < 3; ky++)
                    #pragma unroll
                    for (int kx = 0; kx < 3; kx++) {
                        const float wv = wr[ky*3 + kx];
                        acc[o][0] = fmaf(wv, v[ky  ][kx  ], acc[o][0]);
                        acc[o][1] = fmaf(wv, v[ky  ][kx+1], acc[o][1]);
                        acc[o][2] = fmaf(wv, v[ky+1][kx  ], acc[o][2]);
                        acc[o][3] = fmaf(wv, v[ky+1][kx+1], acc[o][3]);
                    }
            }
        }
    }

    // epilogue: bias + leaky + 2x2 max
    const int py = ty0 + ty;
    const int px = tx0 + tx;
    #pragma unroll
    for (int o = 0; o < OCG; o++) {
        const float bv = bias[ocg*OCG + o];
        float m = -1e30f;
        #pragma unroll
        for (int k = 0; k < 4; k++) {
            float y = acc[o][k] + bv;
            y = (y > 0.f) ? y : 0.01f * y;
            m = fmaxf(m, y);
        }
        out[(((long)b*OCH + ocg*OCG + o) * HP + py) * HP + px] = m;
    }
}

// ---------------------------------------------------------------------------
// FC: out[b,j] = sum_k h[b,k]*wfc[k,j] + bfc[j], two-pass deterministic.
// ---------------------------------------------------------------------------
__global__ void fc_partial(const float* __restrict__ h,
                           const float* __restrict__ w,
                           float* __restrict__ part)
{
    const int chunk = blockIdx.x;          // 98
    const int b     = blockIdx.y;          // 32
    const int tid   = threadIdx.x;         // 256
    const float* hp = h + (long)b * FLATK + chunk * CHUNK;
    const float* wp = w + (long)chunk * CHUNK * 10;

    float acc[10];
    #pragma unroll
    for (int j = 0; j < 10; j++) acc[j] = 0.f;

    for (int i = tid; i < CHUNK; i += 256) {
        const float hv = hp[i];
        const float* wr = wp + i * 10;
        #pragma unroll
        for (int j = 0; j < 10; j++) acc[j] = fmaf(hv, wr[j], acc[j]);
    }

    #pragma unroll
    for (int j = 0; j < 10; j++)
        #pragma unroll
        for (int off = 16; off; off >>= 1)
            acc[j] += __shfl_down_sync(0xffffffffu, acc[j], off);

    __shared__ float sred[8][10];
    const int warp = tid >> 5, lane = tid & 31;
    if (lane == 0) {
        #pragma unroll
        for (int j = 0; j < 10; j++) sred[warp][j] = acc[j];
    }
    __syncthreads();
    if (tid < 10) {
        float s = 0.f;
        #pragma unroll
        for (int w8 = 0; w8 < 8; w8++) s += sred[w8][tid];
        part[(b * NCHUNK + chunk) * 10 + tid] = s;
    }
}

__global__ void fc_combine(const float* __restrict__ part,
                           const float* __restrict__ bfc,
                           float* __restrict__ out)
{
    const int i = blockIdx.x * 64 + threadIdx.x;
    if (i >= NB * 10) return;
    const int b = i / 10, j = i % 10;
    float s = bfc[j];
    for (int c = 0; c < NCHUNK; c++) s += part[(b * NCHUNK + c) * 10 + j];
    out[i] = s;
}

// ---------------------------------------------------------------------------
extern "C" void kernel_launch(void* const* d_in, const int* in_sizes, int n_in,
                              void* d_out, int out_size)
{
    const float* x   = (const float*)d_in[0];
    const float* w1  = (const float*)d_in[1];
    const float* b1  = (const float*)d_in[2];
    const float* w2  = (const float*)d_in[3];
    const float* b2  = (const float*)d_in[4];
    const float* wfc = (const float*)d_in[5];
    const float* bfc = (const float*)d_in[6];
    float* out = (float*)d_out;

    float *h1, *h2, *fcp;
    cudaGetSymbolAddress((void**)&h1,  g_h1);
    cudaGetSymbolAddress((void**)&h2,  g_h2);
    cudaGetSymbolAddress((void**)&fcp, g_fcp);

    // conv1: 32 b * 8 ocg * 64 tiles = 16384 blocks
    conv_lrelu_pool<C1, C1, HA><<<NB * (OCH/OCG) * 8*8, TS*TS>>>(x, w1, b1, h1);
    // conv2: 32 b * 8 ocg * 16 tiles = 4096 blocks
    conv_lrelu_pool<OCH, 8, HB><<<NB * (OCH/OCG) * 4*4, TS*TS>>>(h1, w2, b2, h2);
    // FC
    fc_partial<<<dim3(NCHUNK, NB), 256>>>(h2, wfc, fcp);
    fc_combine<<<5, 64>>>(fcp, bfc, out);
}

// round 3
// speedup vs baseline: 1.8907x; 1.8907x over previous
#include <cuda_runtime.h>
#include <cstdint>

// ---------------------------------------------------------------------------
// SimpleCnn: conv(3->64,3x3,p1)+leaky+pool2 -> conv(64->64,3x3,p1)+leaky+pool2
//            -> flatten -> FC(200704->10)
// conv1: fp32 SIMT (validated).  conv2: tf32 mma.sync implicit GEMM.
// ---------------------------------------------------------------------------

#define NB   32
#define C1   3
#define OCH  64
#define HA   224
#define HB   112
#define HC   56
#define FLATK (OCH*HC*HC)   // 200704
#define NCHUNK 98
#define CHUNK  2048

__device__ float g_h1[NB*OCH*HB*HB];          // 102.8 MB
__device__ float g_h2[NB*OCH*HC*HC];          //  25.7 MB
__device__ float g_fcp[NB*NCHUNK*10];

// ---------------------------------------------------------------------------
// conv1: fused conv3x3 + bias + leaky + pool2 (fp32 SIMT)
// ---------------------------------------------------------------------------
#define TS  14
#define OCG 8

template<int CIN, int ICC, int HIN>
__global__ void __launch_bounds__(TS*TS)
conv_lrelu_pool(const float* __restrict__ x,
                const float* __restrict__ w,
                const float* __restrict__ bias,
                float* __restrict__ out)
{
    constexpr int HP    = HIN / 2;
    constexpr int TILES = HP / TS;

    __shared__ float s_in[ICC][30][32];
    __shared__ float s_w[OCG*ICC*9];

    const int bidx = blockIdx.x;
    const int tile = bidx % (TILES*TILES);
    const int ocg  = (bidx / (TILES*TILES)) % (OCH/OCG);
    const int b    =  bidx / (TILES*TILES*(OCH/OCG));
    const int ty0  = (tile / TILES) * TS;
    const int tx0  = (tile % TILES) * TS;

    const int tid = threadIdx.x;
    const int tx  = tid % TS;
    const int ty  = tid / TS;

    float acc[OCG][4];
    #pragma unroll
    for (int o = 0; o < OCG; o++)
        #pragma unroll
        for (int k = 0; k < 4; k++) acc[o][k] = 0.f;

    const float* xb = x + (long)b * CIN * HIN * HIN;

    for (int c0 = 0; c0 < CIN; c0 += ICC) {
        __syncthreads();
        for (int i = tid; i < ICC*30*30; i += TS*TS) {
            const int c  = i / 900;
            const int r  = (i % 900) / 30;
            const int cc = i % 30;
            const int gy = 2*ty0 - 1 + r;
            const int gx = 2*tx0 - 1 + cc;
            float v = 0.f;
            if (gy >= 0 && gy < HIN && gx >= 0 && gx < HIN)
                v = xb[(c0 + c) * HIN * HIN + gy * HIN + gx];
            s_in[c][r][cc] = v;
        }
        for (int i = tid; i < OCG*ICC*9; i += TS*TS) {
            const int o = i / (ICC*9);
            const int r = i % (ICC*9);
            const int c = r / 9;
            const int k = r % 9;
            s_w[i] = w[((ocg*OCG + o) * CIN + c0 + c) * 9 + k];
        }
        __syncthreads();

        #pragma unroll
        for (int c = 0; c < ICC; c++) {
            float v[4][4];
            #pragma unroll
            for (int i = 0; i < 4; i++)
                #pragma unroll
                for (int j = 0; j < 4; j++)
                    v[i][j] = s_in[c][2*ty + i][2*tx + j];

            #pragma unroll
            for (int o = 0; o < OCG; o++) {
                float wr[9];
                #pragma unroll
                for (int k = 0; k < 9; k++) wr[k] = s_w[(o*ICC + c)*9 + k];
                #pragma unroll
                for (int ky = 0; ky < 3; ky++)
                    #pragma unroll
                    for (int kx = 0; kx < 3; kx++) {
                        const float wv = wr[ky*3 + kx];
                        acc[o][0] = fmaf(wv, v[ky  ][kx  ], acc[o][0]);
                        acc[o][1] = fmaf(wv, v[ky  ][kx+1], acc[o][1]);
                        acc[o][2] = fmaf(wv, v[ky+1][kx  ], acc[o][2]);
                        acc[o][3] = fmaf(wv, v[ky+1][kx+1], acc[o][3]);
                    }
            }
        }
    }

    const int py = ty0 + ty;
    const int px = tx0 + tx;
    #pragma unroll
    for (int o = 0; o < OCG; o++) {
        const float bv = bias[ocg*OCG + o];
        float m = -1e30f;
        #pragma unroll
        for (int k = 0; k < 4; k++) {
            float y = acc[o][k] + bv;
            y = (y > 0.f) ? y : 0.01f * y;
            m = fmaxf(m, y);
        }
        out[(((long)b*OCH + ocg*OCG + o) * HP + py) * HP + px] = m;
    }
}

// ---------------------------------------------------------------------------
// conv2 via tf32 mma.sync.m16n8k8 implicit GEMM, fused bias+leaky+pool2.
// Block: (batch b, conv-row pair pr). M=224 pixels (2 rows x 112 cols),
// N=64 oc, K=576 (8 ic-chunks x 9 taps x 8 ic). 7 warps; warp owns a 16-col
// strip (both conv rows) x all 64 oc.
// ---------------------------------------------------------------------------
__device__ __forceinline__ uint32_t to_tf32(float f) {
    uint32_t u;
    asm("cvt.rna.tf32.f32 %0, %1;" : "=r"(u) : "f"(f));
    return u;
}

__device__ __forceinline__ void mma_tf32(float* c,
                                         uint32_t a0, uint32_t a1, uint32_t a2, uint32_t a3,
                                         uint32_t b0, uint32_t b1) {
    asm volatile("mma.sync.aligned.m16n8k8.row.col.f32.tf32.tf32.f32 "
                 "{%0,%1,%2,%3}, {%4,%5,%6,%7}, {%8,%9}, {%0,%1,%2,%3};"
                 : "+f"(c[0]), "+f"(c[1]), "+f"(c[2]), "+f"(c[3])
                 : "r"(a0), "r"(a1), "r"(a2), "r"(a3), "r"(b0), "r"(b1));
}

#define SWZ(cc, ic) ((((ic) ^ ((cc) >> 2)) & 7))

__global__ void __launch_bounds__(224)
conv2_mma(const float* __restrict__ h1,
          const float* __restrict__ w2,
          const float* __restrict__ bias,
          float* __restrict__ out)
{
    __shared__ uint32_t s_in[4*114*8];    // [row][cc][ic^swz], tf32 bits
    __shared__ uint32_t s_w[9*64*9];      // [tap][oc][ic pad9], tf32 bits

    const int b    = blockIdx.x / 56;
    const int pr   = blockIdx.x % 56;
    const int r0   = 2 * pr;
    const int tid  = threadIdx.x;
    const int lane = tid & 31;
    const int warp = tid >> 5;            // 0..6
    const int colbase = warp * 16;
    const int kb = lane & 3;              // k-lane within group
    const int qr = lane >> 2;             // 0..7

    float c[2][8][4];
    #pragma unroll
    for (int mt = 0; mt < 2; mt++)
        #pragma unroll
        for (int n = 0; n < 8; n++)
            #pragma unroll
            for (int i = 0; i < 4; i++) c[mt][n][i] = 0.f;

    const float* h1b = h1 + (long)b * OCH * HB * HB;

    for (int ic0 = 0; ic0 < 64; ic0 += 8) {
        __syncthreads();
        // stage input rows r0-1..r0+2, cols -1..112, 8 ics (tf32)
        for (int i = tid; i < 8*4*114; i += 224) {
            const int ic  = i / 456;
            const int rem = i % 456;
            const int row = rem / 114;
            const int cc  = rem % 114;
            const int gr  = r0 - 1 + row;
            const int gc  = cc - 1;
            float v = 0.f;
            if (gr >= 0 && gr < HB && gc >= 0 && gc < HB)
                v = h1b[(ic0 + ic) * HB * HB + gr * HB + gc];
            s_in[(row*114 + cc)*8 + SWZ(cc, ic)] = to_tf32(v);
        }
        // stage weights: [tap][oc][ic] for this ic-chunk
        for (int i = tid; i < 9*64*8; i += 224) {
            const int ic  = i & 7;
            const int row = i >> 3;        // tap*64 + oc
            const int tap = row >> 6;
            const int oc  = row & 63;
            s_w[row*9 + ic] = to_tf32(w2[(oc*64 + ic0 + ic)*9 + tap]);
        }
        __syncthreads();

        for (int tap = 0; tap < 9; tap++) {
            const int ky = tap / 3, kx = tap % 3;
            // B fragments (k=ic, n=oc): b0 k=kb, b1 k=kb+4, n = 8*n + qr
            uint32_t bf0[8], bf1[8];
            const uint32_t* swp = s_w + tap * 64 * 9;
            #pragma unroll
            for (int n = 0; n < 8; n++) {
                bf0[n] = swp[(n*8 + qr)*9 + kb];
                bf1[n] = swp[(n*8 + qr)*9 + kb + 4];
            }
            #pragma unroll
            for (int mt = 0; mt < 2; mt++) {
                const int irow = mt + ky;                 // staged row 0..3
                const int cc0  = colbase + qr + kx;       // pixel col + kx
                const int cc1  = cc0 + 8;
                const uint32_t a0 = s_in[(irow*114 + cc0)*8 + SWZ(cc0, kb)];
                const uint32_t a1 = s_in[(irow*114 + cc1)*8 + SWZ(cc1, kb)];
                const uint32_t a2 = s_in[(irow*114 + cc0)*8 + SWZ(cc0, kb + 4)];
                const uint32_t a3 = s_in[(irow*114 + cc1)*8 + SWZ(cc1, kb + 4)];
                #pragma unroll
                for (int n = 0; n < 8; n++)
                    mma_tf32(c[mt][n], a0, a1, a2, a3, bf0[n], bf1[n]);
            }
        }
    }

    // epilogue: bias + leaky + 2x2 maxpool (rows via mt frags, cols via shfl)
    #pragma unroll
    for (int n = 0; n < 8; n++) {
        #pragma unroll
        for (int half = 0; half < 2; half++) {
            #pragma unroll
            for (int j = 0; j < 2; j++) {
                const int i  = half*2 + j;
                const int oc = n*8 + 2*kb + j;
                const float bv = bias[oc];
                float v0 = c[0][n][i] + bv; v0 = (v0 > 0.f) ? v0 : 0.01f * v0;
                float v1 = c[1][n][i] + bv; v1 = (v1 > 0.f) ? v1 : 0.01f * v1;
                float m = fmaxf(v0, v1);
                const float o = __shfl_xor_sync(0xffffffffu, m, 4);
                m = fmaxf(m, o);
                if ((qr & 1) == 0) {
                    const int p  = colbase + qr + half*8;   // even pixel col
                    const int pc = p >> 1;
                    out[((long)(b*OCH + oc)*HC + pr)*HC + pc] = m;
                }
            }
        }
    }
}

// ---------------------------------------------------------------------------
// FC: two-pass deterministic
// ---------------------------------------------------------------------------
__global__ void fc_partial(const float* __restrict__ h,
                           const float* __restrict__ w,
                           float* __restrict__ part)
{
    const int chunk = blockIdx.x;
    const int b     = blockIdx.y;
    const int tid   = threadIdx.x;
    const float* hp = h + (long)b * FLATK + chunk * CHUNK;
    const float* wp = w + (long)chunk * CHUNK * 10;

    float acc[10];
    #pragma unroll
    for (int j = 0; j < 10; j++) acc[j] = 0.f;

    for (int i = tid; i < CHUNK; i += 256) {
        const float hv = hp[i];
        const float* wr = wp + i * 10;
        #pragma unroll
        for (int j = 0; j < 10; j++) acc[j] = fmaf(hv, wr[j], acc[j]);
    }

    #pragma unroll
    for (int j = 0; j < 10; j++)
        #pragma unroll
        for (int off = 16; off; off >>= 1)
            acc[j] += __shfl_down_sync(0xffffffffu, acc[j], off);

    __shared__ float sred[8][10];
    const int warp = tid >> 5, lane = tid & 31;
    if (lane == 0) {
        #pragma unroll
        for (int j = 0; j < 10; j++) sred[warp][j] = acc[j];
    }
    __syncthreads();
    if (tid < 10) {
        float s = 0.f;
        #pragma unroll
        for (int w8 = 0; w8 < 8; w8++) s += sred[w8][tid];
        part[(b * NCHUNK + chunk) * 10 + tid] = s;
    }
}

__global__ void fc_combine(const float* __restrict__ part,
                           const float* __restrict__ bfc,
                           float* __restrict__ out)
{
    const int i = blockIdx.x * 64 + threadIdx.x;
    if (i >= NB * 10) return;
    const int b = i / 10, j = i % 10;
    float s = bfc[j];
    for (int c = 0; c < NCHUNK; c++) s += part[(b * NCHUNK + c) * 10 + j];
    out[i] = s;
}

// ---------------------------------------------------------------------------
extern "C" void kernel_launch(void* const* d_in, const int* in_sizes, int n_in,
                              void* d_out, int out_size)
{
    const float* x   = (const float*)d_in[0];
    const float* w1  = (const float*)d_in[1];
    const float* b1  = (const float*)d_in[2];
    const float* w2  = (const float*)d_in[3];
    const float* b2  = (const float*)d_in[4];
    const float* wfc = (const float*)d_in[5];
    const float* bfc = (const float*)d_in[6];
    float* out = (float*)d_out;

    float *h1, *h2, *fcp;
    cudaGetSymbolAddress((void**)&h1,  g_h1);
    cudaGetSymbolAddress((void**)&h2,  g_h2);
    cudaGetSymbolAddress((void**)&fcp, g_fcp);

    conv_lrelu_pool<C1, C1, HA><<<NB * (OCH/OCG) * 8*8, TS*TS>>>(x, w1, b1, h1);
    conv2_mma<<<NB * 56, 224>>>(h1, w2, b2, h2);
    fc_partial<<<dim3(NCHUNK, NB), 256>>>(h2, wfc, fcp);
    fc_combine<<<5, 64>>>(fcp, bfc, out);
}

// round 4
// speedup vs baseline: 3.7999x; 2.0098x over previous
#include <cuda_runtime.h>
#include <cstdint>

// ---------------------------------------------------------------------------
// SimpleCnn: conv1(3->64)+leaky+pool -> conv2(64->64)+leaky+pool -> FC
// Both convs: tf32 mma.sync.m16n8k8 implicit GEMM, fused epilogue.
// ---------------------------------------------------------------------------

#define NB   32
#define OCH  64
#define HB   112
#define HC   56
#define FLATK (OCH*HC*HC)   // 200704
#define NCHUNK 98
#define CHUNK  2048

__device__ float g_h1[NB*OCH*HB*HB];          // 102.8 MB
__device__ float g_h2[NB*OCH*HC*HC];          //  25.7 MB
__device__ float g_fcp[NB*NCHUNK*10];

__device__ __forceinline__ uint32_t to_tf32(float f) {
    uint32_t u;
    asm("cvt.rna.tf32.f32 %0, %1;" : "=r"(u) : "f"(f));
    return u;
}

__device__ __forceinline__ void mma_tf32(float* c,
                                         uint32_t a0, uint32_t a1, uint32_t a2, uint32_t a3,
                                         uint32_t b0, uint32_t b1) {
    asm volatile("mma.sync.aligned.m16n8k8.row.col.f32.tf32.tf32.f32 "
                 "{%0,%1,%2,%3}, {%4,%5,%6,%7}, {%8,%9}, {%0,%1,%2,%3};"
                 : "+f"(c[0]), "+f"(c[1]), "+f"(c[2]), "+f"(c[3])
                 : "r"(a0), "r"(a1), "r"(a2), "r"(a3), "r"(b0), "r"(b1));
}

#define SWZ(cc, ic) ((((ic) ^ ((cc) >> 2)) & 7))

// ---------------------------------------------------------------------------
// conv1: x[32,3,224,224] -> h1[32,64,112,112].  tf32 MMA, K=27 padded to 32.
// Block: (b, pooled row pr). 448 threads = 14 warps, warp = 16-col strip.
// ---------------------------------------------------------------------------
__global__ void __launch_bounds__(448, 1)
conv1_mma(const float* __restrict__ x,
          const float* __restrict__ w1,
          const float* __restrict__ bias,
          float* __restrict__ out)
{
    __shared__ uint32_t s_in[3*929];   // [ic (stride 929)][row (stride 232)][cc 0..225]
    __shared__ uint32_t s_w[64*33];    // [oc][k pad 33]; k = ic*9 + tap, k>=27 -> 0

    const int b    = blockIdx.x / 112;
    const int pr   = blockIdx.x % 112;
    const int r0   = 2 * pr;
    const int tid  = threadIdx.x;
    const int lane = tid & 31;
    const int warp = tid >> 5;                 // 0..13
    const int colbase = warp * 16;
    const int kb = lane & 3;
    const int qr = lane >> 2;

    // ---- weights once: s_w[oc*33 + k] ----
    #pragma unroll
    for (int e = 0; e < 5; e++) {
        const int idx = tid + 448*e;
        if (idx < 2048) {
            const int oc = idx >> 5, k = idx & 31;
            const float v = (k < 27) ? w1[oc*27 + k] : 0.f;
            s_w[oc*33 + k] = to_tf32(v);
        }
    }
    // ---- halo zeros (cc = 0 and 225) ----
    if (tid < 24) {
        const int ic = tid >> 3, rem = tid & 7;
        const int row = rem >> 1, side = rem & 1;
        s_in[ic*929 + row*232 + (side ? 225 : 0)] = 0;
    }

    // ---- input staging: 3 ic x 4 rows x 56 float4, batched loads ----
    const float* xb = x + (long)b * 3 * 224 * 224;
    float4 v0 = make_float4(0.f,0.f,0.f,0.f);
    float4 v1 = make_float4(0.f,0.f,0.f,0.f);
    const int i0 = tid;
    const int j0 = i0 % 56, row0 = (i0/56) & 3, ic0i = i0/224;
    const int gr0 = r0 - 1 + row0;
    const bool p1 = (tid < 224);
    const int i1 = tid + 448;
    const int j1 = i1 % 56, row1 = (i1/56) & 3, ic1i = i1/224;
    const int gr1 = r0 - 1 + row1;
    if (gr0 >= 0 && gr0 < 224)
        v0 = *((const float4*)(xb + ic0i*224*224 + gr0*224) + j0);
    if (p1 && gr1 >= 0 && gr1 < 224)
        v1 = *((const float4*)(xb + ic1i*224*224 + gr1*224) + j1);
    {
        const int ba = ic0i*929 + row0*232 + 4*j0 + 1;
        s_in[ba+0] = to_tf32(v0.x); s_in[ba+1] = to_tf32(v0.y);
        s_in[ba+2] = to_tf32(v0.z); s_in[ba+3] = to_tf32(v0.w);
        if (p1) {
            const int bb = ic1i*929 + row1*232 + 4*j1 + 1;
            s_in[bb+0] = to_tf32(v1.x); s_in[bb+1] = to_tf32(v1.y);
            s_in[bb+2] = to_tf32(v1.z); s_in[bb+3] = to_tf32(v1.w);
        }
    }

    // ---- per-lane A offsets for each k-group/half ----
    int offk[4][2];
    #pragma unroll
    for (int kg = 0; kg < 4; kg++)
        #pragma unroll
        for (int h = 0; h < 2; h++) {
            const int k = kg*8 + kb + 4*h;
            if (k < 27) {
                const int ic = k / 9;
                const int t9 = k - 9*ic;
                const int ky = t9 / 3;
                const int kx = t9 - 3*ky;
                offk[kg][h] = ic*929 + ky*232 + kx;
            } else offk[kg][h] = 0;   // B is zero for these k; any valid addr
        }

    __syncthreads();

    float c[2][8][4];
    #pragma unroll
    for (int mt = 0; mt < 2; mt++)
        #pragma unroll
        for (int n = 0; n < 8; n++)
            #pragma unroll
            for (int i = 0; i < 4; i++) c[mt][n][i] = 0.f;

    const int abase = colbase + qr;
    #pragma unroll
    for (int kg = 0; kg < 4; kg++) {
        uint32_t bf0[8], bf1[8];
        const int kk = kg*8 + kb;
        #pragma unroll
        for (int n = 0; n < 8; n++) {
            bf0[n] = s_w[(n*8 + qr)*33 + kk];
            bf1[n] = s_w[(n*8 + qr)*33 + kk + 4];
        }
        #pragma unroll
        for (int mt = 0; mt < 2; mt++) {
            const uint32_t a0 = s_in[offk[kg][0] + mt*232 + abase];
            const uint32_t a1 = s_in[offk[kg][0] + mt*232 + abase + 8];
            const uint32_t a2 = s_in[offk[kg][1] + mt*232 + abase];
            const uint32_t a3 = s_in[offk[kg][1] + mt*232 + abase + 8];
            #pragma unroll
            for (int n = 0; n < 8; n++)
                mma_tf32(c[mt][n], a0, a1, a2, a3, bf0[n], bf1[n]);
        }
    }

    // ---- epilogue: bias + leaky + pool2 ----
    #pragma unroll
    for (int n = 0; n < 8; n++)
        #pragma unroll
        for (int half = 0; half < 2; half++)
            #pragma unroll
            for (int j = 0; j < 2; j++) {
                const int i  = half*2 + j;
                const int oc = n*8 + 2*kb + j;
                const float bv = bias[oc];
                float u0 = c[0][n][i] + bv; u0 = (u0 > 0.f) ? u0 : 0.01f*u0;
                float u1 = c[1][n][i] + bv; u1 = (u1 > 0.f) ? u1 : 0.01f*u1;
                float m = fmaxf(u0, u1);
                const float o = __shfl_xor_sync(0xffffffffu, m, 4);
                m = fmaxf(m, o);
                if ((qr & 1) == 0) {
                    const int p  = colbase + qr + half*8;
                    const int pc = p >> 1;
                    out[((long)(b*OCH + oc)*HB + pr)*HB + pc] = m;
                }
            }
}

// ---------------------------------------------------------------------------
// conv2: h1[32,64,112,112] -> h2[32,64,56,56].  tf32 MMA.
// Block: (b, row-block prb of 4 conv rows). 448 threads = 14 warps:
// wq = warp%7 -> 16-col strip, rp = warp/7 -> conv-row pair.
// ---------------------------------------------------------------------------
__global__ void __launch_bounds__(448, 1)
conv2_mma(const float* __restrict__ h1,
          const float* __restrict__ w2,
          const float* __restrict__ bias,
          float* __restrict__ out)
{
    __shared__ uint32_t s_in[6*114*8];    // [row][cc][ic^swz]
    __shared__ uint32_t s_w[9*64*9];      // [tap][oc][ic pad9]

    const int b    = blockIdx.x / 28;
    const int prb  = blockIdx.x % 28;
    const int r0   = 4 * prb;
    const int tid  = threadIdx.x;
    const int lane = tid & 31;
    const int warp = tid >> 5;            // 0..13
    const int wq   = warp % 7;
    const int rp   = warp / 7;            // 0,1
    const int colbase = wq * 16;
    const int kb = lane & 3;
    const int qr = lane >> 2;

    // halo zeros (cc = 0 and 113, all 6 rows, all 8 swz slots)
    if (tid < 96) {
        const int ic = tid & 7, g = tid >> 3;
        const int row = g >> 1, side = g & 1;
        const int cc = side ? 113 : 0;
        s_in[(row*114 + cc)*8 + SWZ(cc, ic)] = 0;
    }

    float c[2][8][4];
    #pragma unroll
    for (int mt = 0; mt < 2; mt++)
        #pragma unroll
        for (int n = 0; n < 8; n++)
            #pragma unroll
            for (int i = 0; i < 4; i++) c[mt][n][i] = 0.f;

    const float* h1b = h1 + (long)b * OCH * HB * HB;

    for (int ic0 = 0; ic0 < 64; ic0 += 8) {
        __syncthreads();
        // ---- input staging: 8 ic x 6 rows x 28 float4 = 1344, 3/thread ----
        float4 va[3];
        #pragma unroll
        for (int it = 0; it < 3; it++) {
            const int i   = tid + 448*it;
            const int j   = i % 28;
            const int row = (i/28) % 6;
            const int ic  = i / 168;
            const int gr  = r0 - 1 + row;
            va[it] = make_float4(0.f,0.f,0.f,0.f);
            if (gr >= 0 && gr < HB)
                va[it] = *((const float4*)(h1b + (ic0 + ic)*HB*HB + gr*HB) + j);
        }
        #pragma unroll
        for (int it = 0; it < 3; it++) {
            const int i   = tid + 448*it;
            const int j   = i % 28;
            const int row = (i/28) % 6;
            const int ic  = i / 168;
            const int cc  = 4*j + 1;
            s_in[(row*114 + cc  )*8 + SWZ(cc,   ic)] = to_tf32(va[it].x);
            s_in[(row*114 + cc+1)*8 + SWZ(cc+1, ic)] = to_tf32(va[it].y);
            s_in[(row*114 + cc+2)*8 + SWZ(cc+2, ic)] = to_tf32(va[it].z);
            s_in[(row*114 + cc+3)*8 + SWZ(cc+3, ic)] = to_tf32(va[it].w);
        }
        // ---- weight staging: 512 (oc,ic) pairs, 9 taps each, batched ----
        {
            const int p0 = tid;                   // < 512 always
            const int oc = p0 >> 3, icl = p0 & 7;
            const float* wp = w2 + (oc*64 + ic0 + icl)*9;
            float wv0[9];
            #pragma unroll
            for (int t = 0; t < 9; t++) wv0[t] = wp[t];
            const int p1 = tid + 448;
            const bool pp = (p1 < 512);
            const int oc2 = (p1 >> 3) & 63, icl2 = p1 & 7;
            const float* wp2 = w2 + (oc2*64 + ic0 + icl2)*9;
            float wv1[9];
            #pragma unroll
            for (int t = 0; t < 9; t++) wv1[t] = pp ? wp2[t] : 0.f;
            #pragma unroll
            for (int t = 0; t < 9; t++) s_w[(t*64 + oc)*9 + icl] = to_tf32(wv0[t]);
            if (pp) {
                #pragma unroll
                for (int t = 0; t < 9; t++) s_w[(t*64 + oc2)*9 + icl2] = to_tf32(wv1[t]);
            }
        }
        __syncthreads();

        #pragma unroll
        for (int tap = 0; tap < 9; tap++) {
            const int ky = tap / 3, kx = tap % 3;
            uint32_t bf0[8], bf1[8];
            const uint32_t* swp = s_w + tap * 576;
            #pragma unroll
            for (int n = 0; n < 8; n++) {
                bf0[n] = swp[(n*8 + qr)*9 + kb];
                bf1[n] = swp[(n*8 + qr)*9 + kb + 4];
            }
            #pragma unroll
            for (int mt = 0; mt < 2; mt++) {
                const int irow = 2*rp + mt + ky;          // 0..5
                const int cc0  = colbase + qr + kx;
                const int cc1  = cc0 + 8;
                const uint32_t a0 = s_in[(irow*114 + cc0)*8 + SWZ(cc0, kb)];
                const uint32_t a1 = s_in[(irow*114 + cc1)*8 + SWZ(cc1, kb)];
                const uint32_t a2 = s_in[(irow*114 + cc0)*8 + SWZ(cc0, kb + 4)];
                const uint32_t a3 = s_in[(irow*114 + cc1)*8 + SWZ(cc1, kb + 4)];
                #pragma unroll
                for (int n = 0; n < 8; n++)
                    mma_tf32(c[mt][n], a0, a1, a2, a3, bf0[n], bf1[n]);
            }
        }
    }

    // ---- epilogue: bias + leaky + pool2; pooled row = 2*prb + rp ----
    const int por = 2*prb + rp;
    #pragma unroll
    for (int n = 0; n < 8; n++)
        #pragma unroll
        for (int half = 0; half < 2; half++)
            #pragma unroll
            for (int j = 0; j < 2; j++) {
                const int i  = half*2 + j;
                const int oc = n*8 + 2*kb + j;
                const float bv = bias[oc];
                float u0 = c[0][n][i] + bv; u0 = (u0 > 0.f) ? u0 : 0.01f*u0;
                float u1 = c[1][n][i] + bv; u1 = (u1 > 0.f) ? u1 : 0.01f*u1;
                float m = fmaxf(u0, u1);
                const float o = __shfl_xor_sync(0xffffffffu, m, 4);
                m = fmaxf(m, o);
                if ((qr & 1) == 0) {
                    const int p  = colbase + qr + half*8;
                    const int pc = p >> 1;
                    out[((long)(b*OCH + oc)*HC + por)*HC + pc] = m;
                }
            }
}

// ---------------------------------------------------------------------------
// FC: two-pass deterministic
// ---------------------------------------------------------------------------
__global__ void fc_partial(const float* __restrict__ h,
                           const float* __restrict__ w,
                           float* __restrict__ part)
{
    const int chunk = blockIdx.x;
    const int b     = blockIdx.y;
    const int tid   = threadIdx.x;
    const float* hp = h + (long)b * FLATK + chunk * CHUNK;
    const float* wp = w + (long)chunk * CHUNK * 10;

    float acc[10];
    #pragma unroll
    for (int j = 0; j < 10; j++) acc[j] = 0.f;

    for (int i = tid; i < CHUNK; i += 256) {
        const float hv = hp[i];
        const float* wr = wp + i * 10;
        #pragma unroll
        for (int j = 0; j < 10; j++) acc[j] = fmaf(hv, wr[j], acc[j]);
    }

    #pragma unroll
    for (int j = 0; j < 10; j++)
        #pragma unroll
        for (int off = 16; off; off >>= 1)
            acc[j] += __shfl_down_sync(0xffffffffu, acc[j], off);

    __shared__ float sred[8][10];
    const int warp = tid >> 5, lane = tid & 31;
    if (lane == 0) {
        #pragma unroll
        for (int j = 0; j < 10; j++) sred[warp][j] = acc[j];
    }
    __syncthreads();
    if (tid < 10) {
        float s = 0.f;
        #pragma unroll
        for (int w8 = 0; w8 < 8; w8++) s += sred[w8][tid];
        part[(b * NCHUNK + chunk) * 10 + tid] = s;
    }
}

__global__ void fc_combine(const float* __restrict__ part,
                           const float* __restrict__ bfc,
                           float* __restrict__ out)
{
    const int i = blockIdx.x * 64 + threadIdx.x;
    if (i >= NB * 10) return;
    const int b = i / 10, j = i % 10;
    float s = bfc[j];
    for (int c = 0; c < NCHUNK; c++) s += part[(b * NCHUNK + c) * 10 + j];
    out[i] = s;
}

// ---------------------------------------------------------------------------
extern "C" void kernel_launch(void* const* d_in, const int* in_sizes, int n_in,
                              void* d_out, int out_size)
{
    const float* x   = (const float*)d_in[0];
    const float* w1  = (const float*)d_in[1];
    const float* b1  = (const float*)d_in[2];
    const float* w2  = (const float*)d_in[3];
    const float* b2  = (const float*)d_in[4];
    const float* wfc = (const float*)d_in[5];
    const float* bfc = (const float*)d_in[6];
    float* out = (float*)d_out;

    float *h1, *h2, *fcp;
    cudaGetSymbolAddress((void**)&h1,  g_h1);
    cudaGetSymbolAddress((void**)&h2,  g_h2);
    cudaGetSymbolAddress((void**)&fcp, g_fcp);

    conv1_mma<<<NB * 112, 448>>>(x, w1, b1, h1);
    conv2_mma<<<NB * 28, 448>>>(h1, w2, b2, h2);
    fc_partial<<<dim3(NCHUNK, NB), 256>>>(h2, wfc, fcp);
    fc_combine<<<5, 64>>>(fcp, bfc, out);
}